// round 14
// baseline (speedup 1.0000x reference)
#include <cuda_runtime.h>

// EMA scan: out[b,t,d] = a*out[b,t-1,d] + (1-a)*x[b,t,d], out[b,-1,d]=0
// Shapes fixed: B=4, S=4096, D=2048, fp32.
//
// Single kernel, CTA owns 32 channels for the whole sequence (traffic
// floor: 268MB). Each thread owns 2 channels as one packed 64-bit float2
// lane; all memory ops are 64-bit (half the LDG/STG/LDS count) and all
// math is packed f32x2 (PTX fma.rn.f32x2 -> FFMA2, half the FMA issue).
// Data stays packed u64 end-to-end. om*x folded once at load so both
// scans are one FFMA2 per step.
// CTA = 256 thr = 16 float2-lanes x 16 sub-chunks of LEN=16; 16 stages,
// 1 barrier/stage, parity-buffered smem, x2 ping-pong prefetch.
// 256 CTAs, 2 CTAs/SM (512 thr/SM -> 128-reg budget).

#define B 4
#define S 4096
#define D 2048
#define D2 (D / 2)             // 1024 float2 columns
#define LANES 16               // float2 lanes per CTA (= 32 channels)
#define SC 16                  // sub-chunks per stage
#define LEN 16                 // timesteps per sub-chunk
#define STAGE_T (SC * LEN)     // 256
#define NSTAGE (S / STAGE_T)   // 16 (even: required by the x2 unroll)
#define TPB (LANES * SC)       // 256

typedef unsigned long long u64;

constexpr float ALPHA = 0.99f;
constexpr float ONEM  = 0.01f;

__host__ __device__ constexpr float pow_alpha(int n) {
    double r = 1.0;
    for (int i = 0; i < n; ++i) r *= 0.99;
    return (float)r;
}

// Pack one float into both f32x2 lanes (compile-time).
__host__ __device__ constexpr u64 packf2(float v) {
    unsigned u = __builtin_bit_cast(unsigned, v);
    return (u64)u | ((u64)u << 32);
}

// DECP2[i] = alpha^(LEN*i) packed into both lanes.
__constant__ u64 DECP2[SC] = {
    packf2(pow_alpha(0)),   packf2(pow_alpha(16)),
    packf2(pow_alpha(32)),  packf2(pow_alpha(48)),
    packf2(pow_alpha(64)),  packf2(pow_alpha(80)),
    packf2(pow_alpha(96)),  packf2(pow_alpha(112)),
    packf2(pow_alpha(128)), packf2(pow_alpha(144)),
    packf2(pow_alpha(160)), packf2(pow_alpha(176)),
    packf2(pow_alpha(192)), packf2(pow_alpha(208)),
    packf2(pow_alpha(224)), packf2(pow_alpha(240))
};

__device__ __forceinline__ u64 fma2(u64 a, u64 b, u64 c) {
    u64 r;
    asm("fma.rn.f32x2 %0, %1, %2, %3;" : "=l"(r) : "l"(a), "l"(b), "l"(c));
    return r;
}
__device__ __forceinline__ u64 mul2(u64 a, u64 b) {
    u64 r;
    asm("mul.rn.f32x2 %0, %1, %2;" : "=l"(r) : "l"(a), "l"(b));
    return r;
}

// One stage: prefetch next tile (pre-scaled by om) into WNXT, scan WCUR,
// exchange carries (compile-time parity P), rescan + store.
#define STAGE_BODY(P, WCUR, WNXT, xn, op, do_pf)                           \
    {                                                                      \
        if (do_pf) {                                                       \
            _Pragma("unroll")                                              \
            for (int j = 0; j < LEN; ++j)                                  \
                WNXT[j] = mul2(OM2, __ldcs(&(xn)[(size_t)j * D2]));        \
        }                                                                  \
        u64 e = 0ull;                                                      \
        _Pragma("unroll")                                                  \
        for (int j = 0; j < LEN; ++j) e = fma2(A2, e, WCUR[j]);            \
        s_ends[P][sc][ch] = e;                                             \
        __syncthreads();                                                   \
        u64 carry = mul2(DECP2[sc], s_carry[P][ch]);                       \
        _Pragma("unroll")                                                  \
        for (int i = 0; i < SC - 1; ++i) {                                 \
            const u64 ei = s_ends[P][i][ch];                               \
            const int idx = sc - 1 - i;                                    \
            const u64 w = (idx >= 0) ? DECP2[idx] : 0ull;                  \
            carry = fma2(w, ei, carry);                                    \
        }                                                                  \
        if (sc == SC - 1)                                                  \
            s_carry[(P) ^ 1][ch] = fma2(DECP2[1], carry, e);               \
        u64 ema = carry;                                                   \
        _Pragma("unroll")                                                  \
        for (int j = 0; j < LEN; ++j) {                                    \
            ema = fma2(A2, ema, WCUR[j]);                                  \
            __stcs(&(op)[(size_t)j * D2], ema);                            \
        }                                                                  \
    }

__global__ void __launch_bounds__(TPB, 2)
ema_cta(const u64* __restrict__ x, u64* __restrict__ out) {
    __shared__ u64 s_ends[2][SC][LANES];   // parity-buffered sub-chunk ends
    __shared__ u64 s_carry[2][LANES];      // parity-buffered stage carry

    const int tid = threadIdx.x;
    const int ch = tid & (LANES - 1);      // float2 lane within CTA
    const int sc = tid >> 4;               // sub-chunk id (0..15)
    const int d2 = blockIdx.x * LANES + ch;
    const int b = blockIdx.y;

    constexpr u64 A2  = packf2(0.99f);
    constexpr u64 OM2 = packf2(0.01f);

    if (tid < LANES) s_carry[0][tid] = 0ull;   // ordered by stage-0 barrier

    // This thread's sub-chunk column base (stage 0); advance by constant.
    const size_t col = (size_t)b * S * D2 + (size_t)sc * LEN * D2 + d2;
    const u64* xp = x + col;
    u64* op = out + col;
    const size_t STRIDE = (size_t)STAGE_T * D2;

    u64 w0[LEN], w1[LEN];
#pragma unroll
    for (int j = 0; j < LEN; ++j)
        w0[j] = mul2(OM2, __ldcs(&xp[(size_t)j * D2]));

#pragma unroll 1
    for (int st = 0; st < NSTAGE; st += 2) {
        // Stage st (parity 0): consume w0, prefetch w1.
        STAGE_BODY(0, w0, w1, xp + STRIDE, op, true)
        xp += STRIDE; op += STRIDE;

        // Stage st+1 (parity 1): consume w1, prefetch w0 (skip on last).
        const bool pf = (st + 2 < NSTAGE);
        STAGE_BODY(1, w1, w0, xp + STRIDE, op, pf)
        xp += STRIDE; op += STRIDE;
    }
}

extern "C" void kernel_launch(void* const* d_in, const int* in_sizes, int n_in,
                              void* d_out, int out_size) {
    const u64* x = (const u64*)d_in[0];
    u64* out = (u64*)d_out;

    dim3 grid(D2 / LANES, B);   // (64, 4) = 256 CTAs
    ema_cta<<<grid, TPB>>>(x, out);
}